// round 17
// baseline (speedup 1.0000x reference)
#include <cuda_runtime.h>
#include <math.h>

#define T_MAXC 1000000
#define NBLK 148                            // 1 block/SM (GB300: 152 SMs) -> co-resident
#define THR 512
#define WARPS (THR / 32)                    // 16
#define U4PL 4                              // uint4 per lane in scan phase
#define U4PW (U4PL * 32)                    // 128 uint4 per warp
#define CHUNK (U4PW * 4 * WARPS)            // 8192 buckets per block
#define T_PAD (NBLK * CHUNK)                // 1212416 (padding stays 0)
#define FPS 2048.0f                         // 2^11 fixed-point scale
#define INV_FPS_F (1.0f / 2048.0f)
#define EMASK 0x00FFFFFFu
#define DESC_FLAG (1ULL << 63)

typedef unsigned long long u64;
typedef unsigned int u32;

// Static device globals (zero at load; every launch restores zeros).
// Packed bucket: bits[0:24) sum(exp x) in 2^-11 fixed point, bits[24:32) event count.
__device__ u32 g_packed[T_PAD];
__device__ volatile u64 g_desc[NBLK];       // chunk aggregate | DESC_FLAG when valid
__device__ double g_evx;
__device__ double g_logterm;
__device__ volatile u32 g_sync1;            // accum->scan grid sync
__device__ u32 g_cnt;                       // completion counter

// ---------------------------------------------------------------------------
// One u32 RED per element (sumexp fixed-point + event count packed).
// ev is exactly 0.0f or 1.0f: bit-trick (0x3F800000>>5)&0x01000000 == 1<<24.
__device__ __forceinline__ void proc(float xv, float tv, float ev, float& evx) {
    int ti = (int)tv;
    ti = min(max(ti, 0), T_MAXC - 1);
    u32 enc = __float2uint_rn(__expf(xv) * FPS)
            + ((__float_as_uint(ev) >> 5) & 0x01000000u);
    atomicAdd(&g_packed[ti], enc);
    evx = fmaf(ev, xv, evx);                // branchless; double at block reduce
}

// ---------------------------------------------------------------------------
__global__ void __launch_bounds__(THR, 1) fused_kernel(const float* __restrict__ x,
                                                       const float* __restrict__ tgt,
                                                       int n, float* __restrict__ out) {
    __shared__ u64 shw[WARPS];
    __shared__ u64 sh2[WARPS];
    __shared__ double shd[WARPS];
    __shared__ u64 sh_look;
    __shared__ bool is_last;

    int tid = threadIdx.x, b = blockIdx.x;
    int lane = tid & 31, wid = tid >> 5;

    // ===================== Phase A: histogram accumulation ==================
    {
        const float4* x4 = reinterpret_cast<const float4*>(x);
        const float4* t4 = reinterpret_cast<const float4*>(tgt);
        int n8 = n >> 3;
        int stride = NBLK * THR;
        float evx = 0.0f;

        for (int i = b * THR + tid; i < n8; i += stride) {
            float4 xa = __ldcg(&x4[2 * i]);
            float4 xb = __ldcg(&x4[2 * i + 1]);
            float4 t0 = __ldcg(&t4[4 * i]);
            float4 t1 = __ldcg(&t4[4 * i + 1]);
            float4 t2 = __ldcg(&t4[4 * i + 2]);
            float4 t3 = __ldcg(&t4[4 * i + 3]);
            proc(xa.x, t0.x, t0.y, evx);
            proc(xa.y, t0.z, t0.w, evx);
            proc(xa.z, t1.x, t1.y, evx);
            proc(xa.w, t1.z, t1.w, evx);
            proc(xb.x, t2.x, t2.y, evx);
            proc(xb.y, t2.z, t2.w, evx);
            proc(xb.z, t3.x, t3.y, evx);
            proc(xb.w, t3.z, t3.w, evx);
        }
        if (b == 0 && tid == 0) {                        // scalar tail
            for (int i = n8 * 8; i < n; i++)
                proc(x[i], tgt[2 * i], tgt[2 * i + 1], evx);
        }

        // block reduce evx (double) -> one global atomic
        double v = (double)evx;
#pragma unroll
        for (int s = 16; s > 0; s >>= 1) v += __shfl_down_sync(0xFFFFFFFFu, v, s);
        if (lane == 0) shd[wid] = v;
        __syncthreads();
        if (tid == 0) {
            double t = 0.0;
#pragma unroll
            for (int w = 0; w < WARPS; w++) t += shd[w];
            atomicAdd(&g_evx, t);
        }
    }

    // ===================== Grid sync (release/acquire) ======================
    if (tid == 0) {
        __threadfence();                                 // release our REDs
        atomicAdd((u32*)&g_sync1, 1u);
        while (g_sync1 < (u32)NBLK) __nanosleep(64);
    }
    __syncthreads();
    __threadfence();                                     // acquire all REDs

    // ===================== Phase B: suffix scan + log walk ==================
    // coalesced loads (L2-hot): lane k owns uint4 (base + j*32 + k)
    uint4* p4 = reinterpret_cast<uint4*>(g_packed);
    int base = b * (CHUNK / 4) + wid * U4PW + lane;
    uint4 r[U4PL];
    u32 s[U4PL];
    u32 local = 0;
#pragma unroll
    for (int j = 0; j < U4PL; j++) {
        r[j] = p4[base + j * 32];
        s[j] = (r[j].x & EMASK) + (r[j].y & EMASK) +
               (r[j].z & EMASK) + (r[j].w & EMASK);
        local += s[j];
    }
#pragma unroll
    for (int j = 0; j < U4PL; j++)
        p4[base + j * 32] = make_uint4(0u, 0u, 0u, 0u);  // re-zero for next launch

    // warp totals -> block aggregate -> publish (single u64 word)
    u32 lv = local;
#pragma unroll
    for (int st = 16; st > 0; st >>= 1) lv += __shfl_down_sync(0xFFFFFFFFu, lv, st);
    if (lane == 0) shw[wid] = (u64)lv;
    __syncthreads();
    if (tid == 0) {
        u64 t = 0;
#pragma unroll
        for (int w = 0; w < WARPS; w++) t += shw[w];
        g_desc[b] = t | DESC_FLAG;
    }

    // lookback: thread t spin-reads aggregate of chunk b+1+t (parallel)
    u64 lb = 0;
    int jj = b + 1 + tid;
    if (jj < NBLK) {
        u64 d = g_desc[jj];
        while (!(d & DESC_FLAG)) { __nanosleep(40); d = g_desc[jj]; }
        lb = d & ~DESC_FLAG;
    }
#pragma unroll
    for (int st = 16; st > 0; st >>= 1) lb += __shfl_down_sync(0xFFFFFFFFu, lb, st);
    if (lane == 0) sh2[wid] = lb;
    __syncthreads();
    if (tid == 0) {
        u64 t = 0;
#pragma unroll
        for (int w = 0; w < WARPS; w++) t += sh2[w];
        sh_look = t;
    }
    __syncthreads();

    // exclusive suffix base for this warp
    u64 woff = 0;
#pragma unroll
    for (int w = 0; w < WARPS; w++)
        if (w > wid) woff += shw[w];
    u64 run_base = sh_look + woff;

    // per-j warp suffix scans interleaved with log walk (float run)
    float contrib = 0.0f;
#pragma unroll
    for (int j = U4PL - 1; j >= 0; j--) {
        u32 v = s[j];
#pragma unroll
        for (int st = 1; st < 32; st <<= 1) {
            u32 o = __shfl_down_sync(0xFFFFFFFFu, v, st);
            if (lane + st < 32) v += o;
        }
        u32 total = __shfl_sync(0xFFFFFFFFu, v, 0);
        float runf = __ull2float_rn(run_base + (u64)(v - s[j]));

        uint4 q = r[j];
        u32 e0 = q.x & EMASK, e1 = q.y & EMASK, e2 = q.z & EMASK, e3 = q.w & EMASK;
        u32 c0 = q.x >> 24,  c1 = q.y >> 24,  c2 = q.z >> 24,  c3 = q.w >> 24;
        runf += (float)e3; if (c3) contrib += (float)c3 * __logf(runf * INV_FPS_F);
        runf += (float)e2; if (c2) contrib += (float)c2 * __logf(runf * INV_FPS_F);
        runf += (float)e1; if (c1) contrib += (float)c1 * __logf(runf * INV_FPS_F);
        runf += (float)e0; if (c0) contrib += (float)c0 * __logf(runf * INV_FPS_F);

        run_base += (u64)total;
    }

    // block reduce contrib (double)
    double cv = (double)contrib;
#pragma unroll
    for (int st = 16; st > 0; st >>= 1) cv += __shfl_down_sync(0xFFFFFFFFu, cv, st);
    if (lane == 0) shd[wid] = cv;
    __syncthreads();
    if (tid == 0) {
        double t = 0.0;
#pragma unroll
        for (int w = 0; w < WARPS; w++) t += shd[w];
        atomicAdd(&g_logterm, t);
        __threadfence();
        is_last = (atomicAdd(&g_cnt, 1u) == (u32)NBLK - 1u);
    }
    __syncthreads();

    // last block: finalize + reset ALL state for graph replay
    if (is_last) {
        if (tid < NBLK) g_desc[tid] = 0ULL;
        if (tid == 0) {
            double lt = atomicAdd(&g_logterm, 0.0);
            double ev = atomicAdd(&g_evx, 0.0);
            out[0] = (float)sqrt((lt - ev) / (double)n);
            g_logterm = 0.0;
            g_evx = 0.0;
            g_cnt = 0u;
            g_sync1 = 0u;
        }
    }
}

// ---------------------------------------------------------------------------
extern "C" void kernel_launch(void* const* d_in, const int* in_sizes, int n_in,
                              void* d_out, int out_size) {
    const float* x   = (const float*)d_in[0];
    const float* tgt = (const float*)d_in[1];
    float* out = (float*)d_out;
    int n = in_sizes[0];

    fused_kernel<<<NBLK, THR>>>(x, tgt, n, out);
}